// round 12
// baseline (speedup 1.0000x reference)
#include <cuda_runtime.h>
#include <cuda_fp16.h>
#include <stdint.h>

// ---------------- problem constants ----------------
constexpr int B = 2, H = 16, S = 2048, D = 64;
constexpr int BH = B * H;
// fold 1/T and log2(e) into Q so exp(s) == exp2(score)
constexpr float SCALE = 1.4426950408889634f / 32.0f;

constexpr int QT = 32;            // query rows per CTA
constexpr int THREADS = 512;      // 16 warps: r2 = w>>3 (row-group), j = w&7 (col-eighth)

// smem layout (bytes)
// [0, 65536)      : 8 pairs x 2 x 4KB streaming buffers (K then V); reused as O slabs in phase E
// [65536, 73728)  : mask bias (2048 floats)
// [73728, 74752)  : row-sum table [32][8]
// [74752, 74880)  : per-row inverse [32]
constexpr int SM_BUF  = 0;
constexpr int SM_MASK = 65536;
constexpr int SM_RST  = SM_MASK + 8192;
constexpr int SM_INV  = SM_RST + 1024;
constexpr int SMEM_SZ = SM_INV + 128;

// ---------------- device fp16 copies ----------------
__device__ __half g_q16[(size_t)BH * S * D];
__device__ __half g_k16[(size_t)BH * S * D];
__device__ __half g_v16[(size_t)BH * S * D];

// ---------------- helpers ----------------
__device__ __forceinline__ uint32_t su32(const void* p) {
    uint32_t a;
    asm("{ .reg .u64 t; cvta.to.shared.u64 t, %1; cvt.u32.u64 %0, t; }" : "=r"(a) : "l"(p));
    return a;
}
__device__ __forceinline__ void cpa16(uint32_t d, const void* s) {
    asm volatile("cp.async.cg.shared.global [%0], [%1], 16;" :: "r"(d), "l"(s));
}
#define CP_COMMIT() asm volatile("cp.async.commit_group;" ::: "memory")
#define CP_WAIT0()  asm volatile("cp.async.wait_group 0;" ::: "memory")
#define NBAR(id)    asm volatile("bar.sync %0, 64;" :: "r"(id) : "memory")

#define LDSM4(r0, r1, r2, r3, a) \
    asm volatile("ldmatrix.sync.aligned.m8n8.x4.shared.b16 {%0,%1,%2,%3}, [%4];" \
                 : "=r"(r0), "=r"(r1), "=r"(r2), "=r"(r3) : "r"(a))
#define LDSM4T(r0, r1, r2, r3, a) \
    asm volatile("ldmatrix.sync.aligned.m8n8.x4.trans.shared.b16 {%0,%1,%2,%3}, [%4];" \
                 : "=r"(r0), "=r"(r1), "=r"(r2), "=r"(r3) : "r"(a))

__device__ __forceinline__ void mma_f16(float4& c, const uint32_t* a,
                                        uint32_t b0, uint32_t b1) {
    asm volatile(
        "mma.sync.aligned.m16n8k16.row.col.f32.f16.f16.f32 "
        "{%0,%1,%2,%3}, {%4,%5,%6,%7}, {%8,%9}, {%0,%1,%2,%3};"
        : "+f"(c.x), "+f"(c.y), "+f"(c.z), "+f"(c.w)
        : "r"(a[0]), "r"(a[1]), "r"(a[2]), "r"(a[3]), "r"(b0), "r"(b1));
}
__device__ __forceinline__ uint32_t packh2(float a, float b) {
    __half2 h = __floats2half2_rn(a, b);
    return *(uint32_t*)&h;
}
__device__ __forceinline__ float2 unpackh2(uint32_t u) {
    return __half22float2(*(__half2*)&u);
}
__device__ __forceinline__ float2 shfl_xor_f2(float2 v, int m) {
    v.x = __shfl_xor_sync(0xffffffffu, v.x, m);
    v.y = __shfl_xor_sync(0xffffffffu, v.y, m);
    return v;
}
// 4x4 transpose of float2 a[4] across a quad of lanes (q = lane&3).
__device__ __forceinline__ void quad_transpose_f2(float2 a[4], int q) {
    {
        float2 v = (q & 1) ? a[0] : a[1];
        v = shfl_xor_f2(v, 1);
        if (q & 1) a[0] = v; else a[1] = v;
        float2 u = (q & 1) ? a[2] : a[3];
        u = shfl_xor_f2(u, 1);
        if (q & 1) a[2] = u; else a[3] = u;
    }
    {
        float2 v = (q & 2) ? a[0] : a[2];
        v = shfl_xor_f2(v, 2);
        if (q & 2) a[0] = v; else a[2] = v;
        float2 u = (q & 2) ? a[1] : a[3];
        u = shfl_xor_f2(u, 2);
        if (q & 2) a[1] = u; else a[3] = u;
    }
}

// 32-key chunk (32 rows x 128B, XOR-swizzled) loaded by one warp (32 lanes x 8 cp.async)
__device__ __forceinline__ void load_chunk(uint32_t dst, const __half* g, int L) {
#pragma unroll
    for (int it = 0; it < 8; it++) {
        int f = L + it * 32;
        int r = f >> 3, c = f & 7;
        cpa16(dst + r * 128 + ((c ^ (r & 7)) << 4), g + r * 64 + c * 8);
    }
}

// ---------------- prep: fp32 -> fp16 (Q scaled by log2e/T) ----------------
__global__ void prep16(const float* __restrict__ q, const float* __restrict__ k,
                       const float* __restrict__ v) {
    const int N4 = BH * S * D / 4;
    int i = blockIdx.x * blockDim.x + threadIdx.x;
    if (i >= N4) return;
    float4 a = ((const float4*)q)[i];
    float4 b = ((const float4*)k)[i];
    float4 c = ((const float4*)v)[i];
    __half2* q2 = (__half2*)g_q16;
    __half2* k2 = (__half2*)g_k16;
    __half2* v2 = (__half2*)g_v16;
    q2[2 * i]     = __floats2half2_rn(a.x * SCALE, a.y * SCALE);
    q2[2 * i + 1] = __floats2half2_rn(a.z * SCALE, a.w * SCALE);
    k2[2 * i]     = __floats2half2_rn(b.x, b.y);
    k2[2 * i + 1] = __floats2half2_rn(b.z, b.w);
    v2[2 * i]     = __floats2half2_rn(c.x, c.y);
    v2[2 * i + 1] = __floats2half2_rn(c.z, c.w);
}

// ---------------- main fused attention (single pass, P in registers) ----------------
__global__ __launch_bounds__(THREADS, 1)
void attn_main(const int* __restrict__ mask,
               float* __restrict__ out, float* __restrict__ attn)
{
    extern __shared__ char smem[];
    const uint32_t sb = su32(smem);
    const int tid = threadIdx.x;
    const int w   = tid >> 5;
    const int L   = tid & 31;
    const int q_  = L & 3;
    const int lrow = L & 7;
    const int lsel = L >> 3;
    const int r2  = w >> 3;          // row-group (rows r2*16 .. +15)
    const int j   = w & 7;           // col-eighth (keys j*256 .. +255)
    const bool prod = (r2 == 0);     // pair producer
    const int bh  = blockIdx.y;
    const int q0  = blockIdx.x * QT;

    const __half* qg = g_q16 + ((size_t)bh * S + q0) * D;
    const __half* kg = g_k16 + (size_t)bh * S * D + (size_t)(j * 256) * D;
    const __half* vg = g_v16 + (size_t)bh * S * D + (size_t)(j * 256) * D;

    const uint32_t buf0 = sb + SM_BUF + j * 8192;
    const uint32_t buf1 = buf0 + 4096;
    float* bf      = (float*)(smem + SM_MASK);
    float* rst     = (float*)(smem + SM_RST);
    float* sInvRow = (float*)(smem + SM_INV);

    // mask -> additive bias
    {
        const int* mp = mask + (size_t)(bh >> 4) * S;
        for (int i = tid; i < S; i += THREADS) bf[i] = mp[i] ? 0.0f : -1e9f;
    }

    // Q fragments direct from global (m16n8k16 A layout), rows r2*16..
    uint32_t qa[4][4];
    {
        const __half* qr0 = qg + (r2 * 16 + (L >> 2)) * 64 + 2 * (L & 3);
        const __half* qr1 = qr0 + 8 * 64;
#pragma unroll
        for (int ks = 0; ks < 4; ks++) {
            qa[ks][0] = *(const uint32_t*)(qr0 + 16 * ks);
            qa[ks][1] = *(const uint32_t*)(qr1 + 16 * ks);
            qa[ks][2] = *(const uint32_t*)(qr0 + 16 * ks + 8);
            qa[ks][3] = *(const uint32_t*)(qr1 + 16 * ks + 8);
        }
    }

    // prologue: producer stages K chunk 0
    if (prod) { load_chunk(buf0, kg, L); CP_COMMIT(); CP_WAIT0(); }
    __syncthreads();   // mask + chunk0 visible

    const uint32_t ksw1 = ((lsel ^ lrow) << 4);
    const uint32_t ksw2 = (((lsel + 4) ^ lrow) << 4);
    const int      c_base = 2 * q_;

    uint32_t P[64];                 // 16 rows x 256 keys of exp'd scores (fp16 fragments)
    float sum_lo = 0.0f, sum_hi = 0.0f;

    // ===== phase A: QK + exp2 + sums, P stays in registers =====
#pragma unroll
    for (int ch = 0; ch < 8; ch++) {
        const uint32_t cbuf = (ch & 1) ? buf1 : buf0;
        const uint32_t nbuf = (ch & 1) ? buf0 : buf1;
        if (prod && ch < 7) { load_chunk(nbuf, kg + (size_t)(ch + 1) * 32 * 64, L); CP_COMMIT(); }
#pragma unroll
        for (int i = 0; i < 4; i++) {
            uint32_t kbase = cbuf + i * 1024 + lrow * 128;
            uint32_t b0, b1, b2, b3, b4, b5, b6, b7;
            LDSM4(b0, b1, b2, b3, kbase + ksw1);
            LDSM4(b4, b5, b6, b7, kbase + ksw2);
            float4 cf = make_float4(0.f, 0.f, 0.f, 0.f);
            mma_f16(cf, qa[0], b0, b1);
            mma_f16(cf, qa[1], b2, b3);
            mma_f16(cf, qa[2], b4, b5);
            mma_f16(cf, qa[3], b6, b7);
            int c0 = j * 256 + ch * 32 + i * 8 + c_base;
            float bi0 = bf[c0], bi1 = bf[c0 + 1];
            float e0 = exp2f(cf.x + bi0);
            float e1 = exp2f(cf.y + bi1);
            float e2 = exp2f(cf.z + bi0);
            float e3 = exp2f(cf.w + bi1);
            sum_lo += e0 + e1;
            sum_hi += e2 + e3;
            P[ch * 8 + (i >> 1) * 4 + (i & 1) * 2]     = packh2(e0, e1);
            P[ch * 8 + (i >> 1) * 4 + (i & 1) * 2 + 1] = packh2(e2, e3);
        }
        if (prod && ch < 7) CP_WAIT0();
        NBAR(1 + j);
    }

    // ===== phase B: row-sum reduction across quads and col-eighths =====
#pragma unroll
    for (int m = 1; m < 4; m <<= 1) {
        sum_lo += __shfl_xor_sync(0xffffffffu, sum_lo, m);
        sum_hi += __shfl_xor_sync(0xffffffffu, sum_hi, m);
    }
    const int row_lo = r2 * 16 + (L >> 2);
    const int row_hi = row_lo + 8;
    if (q_ == 0) {
        rst[row_lo * 8 + j] = sum_lo;
        rst[row_hi * 8 + j] = sum_hi;
    }
    __syncthreads();
    float inv_lo, inv_hi;
    {
        float s0 = 0.f, s1 = 0.f;
#pragma unroll
        for (int t = 0; t < 8; t++) { s0 += rst[row_lo * 8 + t]; s1 += rst[row_hi * 8 + t]; }
        inv_lo = 1.0f / s0;
        inv_hi = 1.0f / s1;
    }
    if (j == 0 && q_ == 0) { sInvRow[row_lo] = inv_lo; sInvRow[row_hi] = inv_hi; }

    // ===== phase C: attn write from register fragments (overlap V chunk0 load) =====
    if (prod) { load_chunk(buf0, vg, L); CP_COMMIT(); }
    {
        float* arow_lo = attn + ((size_t)bh * S + q0 + row_lo) * S;
        float* arow_hi = attn + ((size_t)bh * S + q0 + row_hi) * S;
#pragma unroll
        for (int ch = 0; ch < 8; ch++) {
            float2 flo[4], fhi[4];
#pragma unroll
            for (int i = 0; i < 4; i++) {
                float2 t = unpackh2(P[ch * 8 + i * 2]);
                flo[i] = make_float2(t.x * inv_lo, t.y * inv_lo);
                t = unpackh2(P[ch * 8 + i * 2 + 1]);
                fhi[i] = make_float2(t.x * inv_hi, t.y * inv_hi);
            }
            quad_transpose_f2(flo, q_);
            quad_transpose_f2(fhi, q_);
            int col = j * 256 + ch * 32 + 8 * q_;
            __stcs((float4*)(arow_lo + col),
                   make_float4(flo[0].x, flo[0].y, flo[1].x, flo[1].y));
            __stcs((float4*)(arow_lo + col + 4),
                   make_float4(flo[2].x, flo[2].y, flo[3].x, flo[3].y));
            __stcs((float4*)(arow_hi + col),
                   make_float4(fhi[0].x, fhi[0].y, fhi[1].x, fhi[1].y));
            __stcs((float4*)(arow_hi + col + 4),
                   make_float4(fhi[2].x, fhi[2].y, fhi[3].x, fhi[3].y));
        }
    }
    if (prod) CP_WAIT0();
    NBAR(1 + j);

    // ===== phase D: PV over this warp's 256 keys =====
    float4 oc[8];
#pragma unroll
    for (int nb = 0; nb < 8; nb++) oc[nb] = make_float4(0.f, 0.f, 0.f, 0.f);

#pragma unroll
    for (int ch = 0; ch < 8; ch++) {
        const uint32_t cbuf = (ch & 1) ? buf1 : buf0;
        const uint32_t nbuf = (ch & 1) ? buf0 : buf1;
        if (prod && ch < 7) { load_chunk(nbuf, vg + (size_t)(ch + 1) * 32 * 64, L); CP_COMMIT(); }
#pragma unroll
        for (int nbo = 0; nbo < 8; nbo++) {
            uint32_t vaddr = cbuf + L * 128 + ((nbo ^ lrow) << 4);
            uint32_t v0, v1, v2, v3;
            LDSM4T(v0, v1, v2, v3, vaddr);
            mma_f16(oc[nbo], &P[ch * 8],     v0, v1);
            mma_f16(oc[nbo], &P[ch * 8 + 4], v2, v3);
        }
        if (prod && ch < 7) CP_WAIT0();
        NBAR(1 + j);
    }

    // ===== phase E: cross-warp O reduction via freed buffers =====
    __syncthreads();   // all V reads done; buffers reusable; sInvRow visible
    {
        // slab (r2*8+j): 16 rows x 64 cols fp32
        char* slab = smem + (size_t)(r2 * 8 + j) * 4096;
#pragma unroll
        for (int nb = 0; nb < 8; nb++) {
            int off = (L >> 2) * 256 + (8 * nb + 2 * q_) * 4;
            *(float2*)(slab + off)            = make_float2(oc[nb].x, oc[nb].y);
            *(float2*)(slab + off + 8 * 256)  = make_float2(oc[nb].z, oc[nb].w);
        }
    }
    __syncthreads();
    {
        int row = tid >> 4;            // 0..31
        int d0  = (tid & 15) * 4;      // 0..60
        int rg  = row >> 4, ri = row & 15;
        float4 acc = make_float4(0.f, 0.f, 0.f, 0.f);
#pragma unroll
        for (int jj = 0; jj < 8; jj++) {
            float4 v = *(float4*)(smem + (size_t)(rg * 8 + jj) * 4096 + ri * 256 + d0 * 4);
            acc.x += v.x; acc.y += v.y; acc.z += v.z; acc.w += v.w;
        }
        float inv = sInvRow[row];
        acc.x *= inv; acc.y *= inv; acc.z *= inv; acc.w *= inv;
        *(float4*)(out + ((size_t)bh * S + q0 + row) * D + d0) = acc;
    }
}

// ---------------- launch ----------------
extern "C" void kernel_launch(void* const* d_in, const int* in_sizes, int n_in,
                              void* d_out, int out_size)
{
    const float* q    = (const float*)d_in[0];
    const float* k    = (const float*)d_in[1];
    const float* v    = (const float*)d_in[2];
    const int*   mask = (const int*)  d_in[3];

    float* out  = (float*)d_out;
    float* attn = out + (size_t)BH * S * D;

    cudaFuncSetAttribute(attn_main, cudaFuncAttributeMaxDynamicSharedMemorySize, SMEM_SZ);

    const int N4 = BH * S * D / 4;
    prep16<<<(N4 + 255) / 256, 256>>>(q, k, v);
    attn_main<<<dim3(S / QT, BH), THREADS, SMEM_SZ>>>(mask, out, attn);
}